// round 2
// baseline (speedup 1.0000x reference)
#include <cuda_runtime.h>
#include <math.h>

// Problem constants
#define Bsz 2
#define SQd 256
#define SKd 512
#define Ed  512
#define Hd  256

// Scratch: qf, kf, qp, kp, qv, kv  (device global, no allocation)
#define NQ (Bsz*SQd)   // 512
#define NK (Bsz*SKd)   // 1024
#define OFF_QF 0
#define OFF_KF (OFF_QF + NQ*Hd)
#define OFF_QP (OFF_KF + NK*Hd)
#define OFF_KP (OFF_QP + NQ*Hd)
#define OFF_QV (OFF_KP + NK*Hd)
#define OFF_KV (OFF_QV + NQ*Hd)
#define SCRATCH_FLOATS (OFF_KV + NK*Hd)

__device__ float g_scratch[SCRATCH_FLOATS];

__device__ __forceinline__ float frelu(float x) { return x > 0.f ? x : 0.f; }
__device__ __forceinline__ float4 ldg4(const float* p) { return __ldg((const float4*)p); }

// ---------------------------------------------------------------------------
// Small generic GEMM: C[M,256] = act(A[M,K] @ W[K,256] (+bias))
// Tile: 32 rows x 64 cols per block, 256 threads, K-chunks of 32.
// ---------------------------------------------------------------------------
__global__ void gemm_bias_act_kernel(const float* __restrict__ A,
                                     const float* __restrict__ W,
                                     const float* __restrict__ bias,
                                     float* __restrict__ C,
                                     int M, int K, int act)
{
    __shared__ float As[32 * 32];
    __shared__ float Ws[32 * 64];

    const int tid  = threadIdx.x;
    const int row0 = blockIdx.y * 32;
    const int col0 = blockIdx.x * 64;
    const int tr   = tid >> 4;   // 0..15 -> rows tr*2, tr*2+1
    const int tc   = tid & 15;   // 0..15 -> cols tc*4..tc*4+3

    float acc0x = 0.f, acc0y = 0.f, acc0z = 0.f, acc0w = 0.f;
    float acc1x = 0.f, acc1y = 0.f, acc1z = 0.f, acc1w = 0.f;
    if (bias) {
        float4 bb = ldg4(bias + col0 + tc * 4);
        acc0x = bb.x; acc0y = bb.y; acc0z = bb.z; acc0w = bb.w;
        acc1x = bb.x; acc1y = bb.y; acc1z = bb.z; acc1w = bb.w;
    }

    for (int kc = 0; kc < K; kc += 32) {
        __syncthreads();
        {   // load A chunk: 32 rows x 32 cols
            int r  = tid >> 3;
            int ck = (tid & 7) * 4;
            *(float4*)(As + r * 32 + ck) =
                ldg4(A + (size_t)(row0 + r) * K + kc + ck);
        }
        {   // load W chunk: 32 rows x 64 cols
            #pragma unroll
            for (int i = 0; i < 2; i++) {
                int f = tid + 256 * i;
                int k = f >> 4;
                int c = (f & 15) * 4;
                *(float4*)(Ws + k * 64 + c) =
                    ldg4(W + (size_t)(kc + k) * 256 + col0 + c);
            }
        }
        __syncthreads();

        #pragma unroll 8
        for (int k = 0; k < 32; k++) {
            float a0 = As[(tr * 2) * 32 + k];
            float a1 = As[(tr * 2 + 1) * 32 + k];
            float4 w = *(float4*)(Ws + k * 64 + tc * 4);
            acc0x = fmaf(a0, w.x, acc0x); acc0y = fmaf(a0, w.y, acc0y);
            acc0z = fmaf(a0, w.z, acc0z); acc0w = fmaf(a0, w.w, acc0w);
            acc1x = fmaf(a1, w.x, acc1x); acc1y = fmaf(a1, w.y, acc1y);
            acc1z = fmaf(a1, w.z, acc1z); acc1w = fmaf(a1, w.w, acc1w);
        }
    }

    if (act) {
        acc0x = frelu(acc0x); acc0y = frelu(acc0y); acc0z = frelu(acc0z); acc0w = frelu(acc0w);
        acc1x = frelu(acc1x); acc1y = frelu(acc1y); acc1z = frelu(acc1z); acc1w = frelu(acc1w);
    }
    float4 o0 = make_float4(acc0x, acc0y, acc0z, acc0w);
    float4 o1 = make_float4(acc1x, acc1y, acc1z, acc1w);
    *(float4*)(C + (size_t)(row0 + tr * 2)     * 256 + col0 + tc * 4) = o0;
    *(float4*)(C + (size_t)(row0 + tr * 2 + 1) * 256 + col0 + tc * 4) = o1;
}

// ---------------------------------------------------------------------------
// Fused per-pair MLP kernel.
// Block = (b, q, 64 k-values). hbuf holds h0 -> h1 -> h2 (ping-pong in place).
// ---------------------------------------------------------------------------
#define HSTRIDE 264   // padded row stride (floats), multiple of 4, not mult of 32
#define WCHUNK_OFF (64 * HSTRIDE)
#define SMEM_FLOATS (64 * HSTRIDE + 32 * 256)
#define SMEM_BYTES  (SMEM_FLOATS * 4)

// One [64,256] x [256,256] GEMM with bias + relu; result written back to hbuf.
__device__ __forceinline__ void gemm_step(float* hbuf, float* wchunk,
                                          const float* __restrict__ W,
                                          const float* __restrict__ bias,
                                          int tid)
{
    const int tc = tid & 31;   // col lane: cols tc + 32*jj
    const int tr = tid >> 5;   // row group: rows tr*8 + i

    float acc[64];
    #pragma unroll
    for (int jj = 0; jj < 8; jj++) {
        float bb = __ldg(bias + tc + 32 * jj);
        #pragma unroll
        for (int i = 0; i < 8; i++) acc[i * 8 + jj] = bb;
    }

    for (int kc = 0; kc < Hd; kc += 32) {
        __syncthreads();   // protect wchunk readers of previous chunk / hbuf writers
        #pragma unroll
        for (int i = 0; i < 8; i++) {
            int f4 = tid + 256 * i;   // 0..2047 float4s = 32x256 floats
            ((float4*)wchunk)[f4] = __ldg(((const float4*)(W + kc * 256)) + f4);
        }
        __syncthreads();

        #pragma unroll 8
        for (int k = 0; k < 32; k++) {
            float a[8], bv[8];
            #pragma unroll
            for (int i = 0; i < 8; i++)
                a[i] = hbuf[(tr * 8 + i) * HSTRIDE + kc + k];   // warp broadcast
            #pragma unroll
            for (int jj = 0; jj < 8; jj++)
                bv[jj] = wchunk[k * 256 + tc + 32 * jj];        // conflict-free
            #pragma unroll
            for (int i = 0; i < 8; i++)
                #pragma unroll
                for (int jj = 0; jj < 8; jj++)
                    acc[i * 8 + jj] = fmaf(a[i], bv[jj], acc[i * 8 + jj]);
        }
    }

    __syncthreads();   // all hbuf reads done -> safe to overwrite
    #pragma unroll
    for (int i = 0; i < 8; i++)
        #pragma unroll
        for (int jj = 0; jj < 8; jj++)
            hbuf[(tr * 8 + i) * HSTRIDE + tc + 32 * jj] =
                frelu(acc[i * 8 + jj]);
    __syncthreads();
}

__global__ void pair_kernel(const float* __restrict__ W1, const float* __restrict__ b1,
                            const float* __restrict__ W2, const float* __restrict__ b2,
                            const float* __restrict__ Wf, const float* __restrict__ bf,
                            const float* __restrict__ b0, const float* __restrict__ bv1,
                            const float* __restrict__ Wv2, const float* __restrict__ bv2,
                            float* __restrict__ out)
{
    extern __shared__ float sm[];
    float* hbuf   = sm;
    float* wchunk = sm + WCHUNK_OFF;

    const int tid   = threadIdx.x;
    const int kb    = blockIdx.x;          // 0..7  (64 k's each)
    const int q     = blockIdx.y;          // 0..255
    const int b     = blockIdx.z;          // 0..1
    const int qrow  = b * SQd + q;
    const int krow0 = b * SKd + kb * 64;

    const float* qp = g_scratch + OFF_QP + (size_t)qrow  * Hd;
    const float* kp = g_scratch + OFF_KP + (size_t)krow0 * Hd;
    const float* qv = g_scratch + OFF_QV + (size_t)qrow  * Hd;
    const float* kv = g_scratch + OFF_KV + (size_t)krow0 * Hd;

    // ---- variance branch (no big GEMM): v = relu(qv + kv + bv1); softplus(v.Wv2+bv2)
    {
        const int j = tid >> 2, part = tid & 3;
        const float* qvr = qv + part * 64;
        const float* kvr = kv + (size_t)j * Hd + part * 64;
        const float* bvr = bv1 + part * 64;
        const float* wvr = Wv2 + part * 64;
        float s = 0.f;
        #pragma unroll
        for (int i = 0; i < 16; i++) {
            float4 a = ldg4(qvr + i * 4);
            float4 c = ldg4(kvr + i * 4);
            float4 bb = ldg4(bvr + i * 4);
            float4 w = ldg4(wvr + i * 4);
            s = fmaf(frelu(a.x + c.x + bb.x), w.x, s);
            s = fmaf(frelu(a.y + c.y + bb.y), w.y, s);
            s = fmaf(frelu(a.z + c.z + bb.z), w.z, s);
            s = fmaf(frelu(a.w + c.w + bb.w), w.w, s);
        }
        s += __shfl_down_sync(0xffffffffu, s, 2);
        s += __shfl_down_sync(0xffffffffu, s, 1);
        if (part == 0) {
            float x = s + __ldg(bv2);
            // softplus = max(x,0) + log1p(exp(-|x|))
            out[(size_t)Bsz * SQd * SKd + (size_t)qrow * SKd + kb * 64 + j] =
                fmaxf(x, 0.f) + log1pf(expf(-fabsf(x)));
        }
    }

    // ---- build h0 = relu(qp + kp + b0) into hbuf [64][HSTRIDE]
    #pragma unroll
    for (int s5 = 0; s5 < 16; s5++) {
        int f4 = tid + 256 * s5;     // float4 index over 64x256
        int j  = f4 >> 6;            // row (k index within tile)
        int d  = (f4 & 63) * 4;      // col
        float4 a  = ldg4(qp + d);
        float4 c  = ldg4(kp + (size_t)j * Hd + d);
        float4 bb = ldg4(b0 + d);
        float4 h;
        h.x = frelu(a.x + c.x + bb.x);
        h.y = frelu(a.y + c.y + bb.y);
        h.z = frelu(a.z + c.z + bb.z);
        h.w = frelu(a.w + c.w + bb.w);
        *(float4*)(hbuf + j * HSTRIDE + d) = h;
    }
    // (gemm_step's leading __syncthreads orders hbuf writes before reads)

    gemm_step(hbuf, wchunk, W1, b1, tid);   // h1 = relu(h0 @ W1 + b1)
    gemm_step(hbuf, wchunk, W2, b2, tid);   // h2 = relu(h1 @ W2 + b2)

    // ---- logits = h2 @ Wf + bf
    {
        const int j = tid >> 2, part = tid & 3;
        const float* hr = hbuf + j * HSTRIDE + part * 64;
        const float* wf = Wf + part * 64;
        float s = 0.f;
        #pragma unroll
        for (int i = 0; i < 16; i++) {
            float4 h = *(float4*)(hr + i * 4);
            float4 w = ldg4(wf + i * 4);
            s = fmaf(h.x, w.x, s);
            s = fmaf(h.y, w.y, s);
            s = fmaf(h.z, w.z, s);
            s = fmaf(h.w, w.w, s);
        }
        s += __shfl_down_sync(0xffffffffu, s, 2);
        s += __shfl_down_sync(0xffffffffu, s, 1);
        if (part == 0)
            out[(size_t)qrow * SKd + kb * 64 + j] = s + __ldg(bf);
    }
}

// ---------------------------------------------------------------------------
// Launch
// ---------------------------------------------------------------------------
extern "C" void kernel_launch(void* const* d_in, const int* in_sizes, int n_in,
                              void* d_out, int out_size)
{
    (void)in_sizes; (void)n_in; (void)out_size;
    const float* query = (const float*)d_in[0];   // [2,256,512]
    const float* key_  = (const float*)d_in[1];   // [2,512,512]
    const float* Wqe   = (const float*)d_in[2];   // [512,256]
    const float* bqe   = (const float*)d_in[3];
    const float* Wke   = (const float*)d_in[4];
    const float* bke   = (const float*)d_in[5];
    const float* W0    = (const float*)d_in[6];   // [512,256]
    const float* b0    = (const float*)d_in[7];
    const float* W1    = (const float*)d_in[8];   // [256,256]
    const float* b1    = (const float*)d_in[9];
    const float* W2    = (const float*)d_in[10];
    const float* b2    = (const float*)d_in[11];
    const float* Wf    = (const float*)d_in[12];  // [256]
    const float* bf    = (const float*)d_in[13];
    const float* Wv1   = (const float*)d_in[14];  // [512,256]
    const float* bv1   = (const float*)d_in[15];
    const float* Wv2   = (const float*)d_in[16];  // [256]
    const float* bv2   = (const float*)d_in[17];
    float* out = (float*)d_out;

    void* sp = nullptr;
    cudaGetSymbolAddress(&sp, g_scratch);
    float* S = (float*)sp;

    cudaFuncSetAttribute(pair_kernel,
                         cudaFuncAttributeMaxDynamicSharedMemorySize, SMEM_BYTES);

    // Encoders: qf = relu(query @ Wqe + bqe), kf = relu(key @ Wke + bke)
    gemm_bias_act_kernel<<<dim3(4, NQ / 32), 256>>>(query, Wqe, bqe, S + OFF_QF, NQ, Ed, 1);
    gemm_bias_act_kernel<<<dim3(4, NK / 32), 256>>>(key_,  Wke, bke, S + OFF_KF, NK, Ed, 1);

    // Projections (no bias/act): qp = qf@W0[:H], kp = kf@W0[H:], qv = qf@Wv1[:H], kv = kf@Wv1[H:]
    gemm_bias_act_kernel<<<dim3(4, NQ / 32), 256>>>(S + OFF_QF, W0,            nullptr, S + OFF_QP, NQ, Hd, 0);
    gemm_bias_act_kernel<<<dim3(4, NK / 32), 256>>>(S + OFF_KF, W0 + Hd * Hd,  nullptr, S + OFF_KP, NK, Hd, 0);
    gemm_bias_act_kernel<<<dim3(4, NQ / 32), 256>>>(S + OFF_QF, Wv1,           nullptr, S + OFF_QV, NQ, Hd, 0);
    gemm_bias_act_kernel<<<dim3(4, NK / 32), 256>>>(S + OFF_KF, Wv1 + Hd * Hd, nullptr, S + OFF_KV, NK, Hd, 0);

    // Fused per-pair MLP
    pair_kernel<<<dim3(SKd / 64, SQd, Bsz), 256, SMEM_BYTES>>>(
        W1, b1, W2, b2, Wf, bf, b0, bv1, Wv2, bv2, out);
}

// round 4
// speedup vs baseline: 2.4541x; 2.4541x over previous
#include <cuda_runtime.h>
#include <cuda_bf16.h>
#include <math.h>
#include <cstdint>

// Problem constants
#define Bsz 2
#define SQd 256
#define SKd 512
#define Ed  512
#define Hd  256

#define NQ (Bsz*SQd)   // 512
#define NK (Bsz*SKd)   // 1024
#define OFF_QF 0
#define OFF_KF (OFF_QF + NQ*Hd)
#define OFF_QP (OFF_KF + NK*Hd)
#define OFF_KP (OFF_QP + NQ*Hd)
#define OFF_QV (OFF_KP + NK*Hd)
#define OFF_KV (OFF_QV + NQ*Hd)
#define SCRATCH_FLOATS (OFF_KV + NK*Hd)

__device__ float g_scratch[SCRATCH_FLOATS];
// Transposed + hi/lo split weights: [W1h][W1l][W2h][W2l], each [256 n][256 k] bf16
__device__ __align__(16) __nv_bfloat16 g_wt[4 * 256 * 256];

__device__ __forceinline__ float frelu(float x) { return x > 0.f ? x : 0.f; }
__device__ __forceinline__ float4 ldg4(const float* p) { return __ldg((const float4*)p); }

__device__ __forceinline__ uint32_t smem_to_u32(const void* p) {
    uint32_t a;
    asm("{ .reg .u64 t; cvta.to.shared.u64 t, %1; cvt.u32.u64 %0, t; }" : "=r"(a) : "l"(p));
    return a;
}
__device__ __forceinline__ void cp16(uint32_t dst, const void* src) {
    asm volatile("cp.async.cg.shared.global [%0], [%1], 16;" :: "r"(dst), "l"(src));
}
#define CP_COMMIT() asm volatile("cp.async.commit_group;" ::: "memory")
#define CP_WAIT0()  asm volatile("cp.async.wait_group 0;" ::: "memory")

// mma.sync m16n8k16 bf16 -> f32, accumulate in place
__device__ __forceinline__ void mma_bf16(float* c, const uint32_t* a, const uint32_t* b) {
    asm volatile(
        "mma.sync.aligned.m16n8k16.row.col.f32.bf16.bf16.f32 "
        "{%0,%1,%2,%3}, {%4,%5,%6,%7}, {%8,%9}, {%0,%1,%2,%3};"
        : "+f"(c[0]), "+f"(c[1]), "+f"(c[2]), "+f"(c[3])
        : "r"(a[0]), "r"(a[1]), "r"(a[2]), "r"(a[3]), "r"(b[0]), "r"(b[1]));
}

__device__ __forceinline__ void split2(float x0, float x1, uint32_t& h, uint32_t& l) {
    __nv_bfloat16 h0 = __float2bfloat16(x0), h1 = __float2bfloat16(x1);
    float r0 = x0 - __bfloat162float(h0), r1 = x1 - __bfloat162float(h1);
    __nv_bfloat16 l0 = __float2bfloat16(r0), l1 = __float2bfloat16(r1);
    h = (uint32_t)__bfloat16_as_ushort(h0) | ((uint32_t)__bfloat16_as_ushort(h1) << 16);
    l = (uint32_t)__bfloat16_as_ushort(l0) | ((uint32_t)__bfloat16_as_ushort(l1) << 16);
}

// ---------------------------------------------------------------------------
// Prep GEMM (verified in R2)
// ---------------------------------------------------------------------------
__global__ void gemm_bias_act_kernel(const float* __restrict__ A,
                                     const float* __restrict__ W,
                                     const float* __restrict__ bias,
                                     float* __restrict__ C,
                                     int M, int K, int act)
{
    __shared__ float As[32 * 32];
    __shared__ float Ws[32 * 64];
    const int tid  = threadIdx.x;
    const int row0 = blockIdx.y * 32;
    const int col0 = blockIdx.x * 64;
    const int tr   = tid >> 4;
    const int tc   = tid & 15;

    float acc0x=0.f,acc0y=0.f,acc0z=0.f,acc0w=0.f,acc1x=0.f,acc1y=0.f,acc1z=0.f,acc1w=0.f;
    if (bias) {
        float4 bb = ldg4(bias + col0 + tc * 4);
        acc0x=bb.x;acc0y=bb.y;acc0z=bb.z;acc0w=bb.w;
        acc1x=bb.x;acc1y=bb.y;acc1z=bb.z;acc1w=bb.w;
    }
    for (int kc = 0; kc < K; kc += 32) {
        __syncthreads();
        {   int r = tid >> 3; int ck = (tid & 7) * 4;
            *(float4*)(As + r * 32 + ck) = ldg4(A + (size_t)(row0 + r) * K + kc + ck); }
        {
            #pragma unroll
            for (int i = 0; i < 2; i++) {
                int f = tid + 256 * i; int k = f >> 4; int c = (f & 15) * 4;
                *(float4*)(Ws + k * 64 + c) = ldg4(W + (size_t)(kc + k) * 256 + col0 + c);
            } }
        __syncthreads();
        #pragma unroll 8
        for (int k = 0; k < 32; k++) {
            float a0 = As[(tr * 2) * 32 + k];
            float a1 = As[(tr * 2 + 1) * 32 + k];
            float4 w = *(float4*)(Ws + k * 64 + tc * 4);
            acc0x = fmaf(a0, w.x, acc0x); acc0y = fmaf(a0, w.y, acc0y);
            acc0z = fmaf(a0, w.z, acc0z); acc0w = fmaf(a0, w.w, acc0w);
            acc1x = fmaf(a1, w.x, acc1x); acc1y = fmaf(a1, w.y, acc1y);
            acc1z = fmaf(a1, w.z, acc1z); acc1w = fmaf(a1, w.w, acc1w);
        }
    }
    if (act) {
        acc0x=frelu(acc0x);acc0y=frelu(acc0y);acc0z=frelu(acc0z);acc0w=frelu(acc0w);
        acc1x=frelu(acc1x);acc1y=frelu(acc1y);acc1z=frelu(acc1z);acc1w=frelu(acc1w);
    }
    *(float4*)(C + (size_t)(row0+tr*2)  *256 + col0 + tc*4) = make_float4(acc0x,acc0y,acc0z,acc0w);
    *(float4*)(C + (size_t)(row0+tr*2+1)*256 + col0 + tc*4) = make_float4(acc1x,acc1y,acc1z,acc1w);
}

// Transpose + hi/lo bf16 split of W1, W2 into g_wt (Wt[n][k] row-major)
__global__ void transpose_split_kernel(const float* __restrict__ W1,
                                       const float* __restrict__ W2)
{
    const float* W = blockIdx.x ? W2 : W1;
    __nv_bfloat16* oh = g_wt + (size_t)blockIdx.x * 2 * 65536;
    __nv_bfloat16* ol = oh + 65536;
    int base = blockIdx.y * 1024;    // grid.y = 64
    #pragma unroll
    for (int t = 0; t < 4; t++) {
        int e = base + t * 256 + threadIdx.x;
        int n = e >> 8, k = e & 255;
        float w = __ldg(W + (size_t)k * 256 + n);
        __nv_bfloat16 h = __float2bfloat16(w);
        __nv_bfloat16 l = __float2bfloat16(w - __bfloat162float(h));
        oh[e] = h; ol[e] = l;
    }
}

// ---------------------------------------------------------------------------
// HMMA fused pair kernel. CTA = (b, q, 128 k-pairs). M=128, N=256, K=256.
// 8 warps: 2 (M, 64 each) x 4 (N, 64 each). 3-term bf16 split GEMM.
// ---------------------------------------------------------------------------
#define APITCH 264                       // bf16 elems per A row (528 B)
#define WPITCH 40                        // bf16 elems per W chunk row (80 B)
#define SM_AH 0
#define SM_AL (128 * APITCH * 2)         // 67584
#define SM_W  (2 * 128 * APITCH * 2)     // 135168
#define WBUF_BYTES (256 * WPITCH * 2)    // 20480 (one of H/L)
#define SM_PART (SM_W + 4 * WBUF_BYTES)  // 217088
#define SMEM_TOTAL (SM_PART + 512 * 4)   // 219136

__global__ void __launch_bounds__(256, 1)
pair_mma_kernel(const float* __restrict__ b0, const float* __restrict__ b1,
                const float* __restrict__ b2,
                const float* __restrict__ Wf, const float* __restrict__ bf,
                const float* __restrict__ bv1, const float* __restrict__ Wv2,
                const float* __restrict__ bv2,
                float* __restrict__ out)
{
    extern __shared__ char smem[];
    const uint32_t sbase = smem_to_u32(smem);

    const int tid = threadIdx.x;
    const int w   = tid >> 5;
    const int wm  = w >> 2;            // 0..1 : M group (64 rows)
    const int wn  = w & 3;             // 0..3 : N group (64 cols)
    const int lt  = tid & 31;
    const int lrow = lt >> 2;          // 0..7
    const int lc2  = (lt & 3) * 2;     // 0,2,4,6

    const int kb = blockIdx.x, q = blockIdx.y, b = blockIdx.z;
    const int qrow  = b * SQd + q;
    const int krow0 = b * SKd + kb * 128;

    const float* qp = g_scratch + OFF_QP + (size_t)qrow  * Hd;
    const float* kp = g_scratch + OFF_KP + (size_t)krow0 * Hd;
    const float* qv = g_scratch + OFF_QV + (size_t)qrow  * Hd;
    const float* kv = g_scratch + OFF_KV + (size_t)krow0 * Hd;

    // ---- prefetch W chunk 0 (layer 0) via cp.async while we do fp32 work
    {
        #pragma unroll
        for (int it = 0; it < 8; it++) {
            int u = tid + (it & 3) * 256;       // 0..1023
            int n = u >> 2, j = u & 3;
            const __nv_bfloat16* src = g_wt + (it < 4 ? 0 : 65536) + n * 256 + 0 * 32 + j * 8;
            uint32_t dst = sbase + SM_W + (it < 4 ? 0 : WBUF_BYTES) + n * 80 + j * 16;
            cp16(dst, src);
        }
        CP_COMMIT();
    }

    // ---- variance branch: v = relu(qv+kv+bv1); softplus(v.Wv2 + bv2)
    {
        const int r = tid >> 1, part = tid & 1;
        const float* qvr = qv + part * 128;
        const float* kvr = kv + (size_t)r * Hd + part * 128;
        const float* bvr = bv1 + part * 128;
        const float* wvr = Wv2 + part * 128;
        float s = 0.f;
        #pragma unroll
        for (int i = 0; i < 32; i++) {
            float4 a = ldg4(qvr + i * 4);
            float4 c = ldg4(kvr + i * 4);
            float4 bb = ldg4(bvr + i * 4);
            float4 ww = ldg4(wvr + i * 4);
            s = fmaf(frelu(a.x + c.x + bb.x), ww.x, s);
            s = fmaf(frelu(a.y + c.y + bb.y), ww.y, s);
            s = fmaf(frelu(a.z + c.z + bb.z), ww.z, s);
            s = fmaf(frelu(a.w + c.w + bb.w), ww.w, s);
        }
        s += __shfl_down_sync(0xffffffffu, s, 1);
        if (part == 0) {
            float x = s + __ldg(bv2);
            out[(size_t)Bsz * SQd * SKd + (size_t)qrow * SKd + kb * 128 + r] =
                fmaxf(x, 0.f) + log1pf(expf(-fabsf(x)));
        }
    }

    // ---- build A = relu(qp + kp + b0), hi/lo split -> SMEM
    {
        const int row = tid >> 1, half = (tid & 1) * 128;
        const float* qpr = qp + half;
        const float* kpr = kp + (size_t)row * Hd + half;
        const float* b0r = b0 + half;
        #pragma unroll
        for (int j4 = 0; j4 < 32; j4++) {
            float4 a  = ldg4(qpr + j4 * 4);
            float4 c  = ldg4(kpr + j4 * 4);
            float4 bb = ldg4(b0r + j4 * 4);
            float x0 = frelu(a.x + c.x + bb.x);
            float x1 = frelu(a.y + c.y + bb.y);
            float x2 = frelu(a.z + c.z + bb.z);
            float x3 = frelu(a.w + c.w + bb.w);
            uint32_t h0, l0, h1, l1;
            split2(x0, x1, h0, l0);
            split2(x2, x3, h1, l1);
            uint32_t off = (uint32_t)row * (APITCH * 2) + (half + j4 * 4) * 2;
            *(uint2*)(smem + SM_AH + off) = make_uint2(h0, h1);
            *(uint2*)(smem + SM_AL + off) = make_uint2(l0, l1);
        }
    }
    CP_WAIT0();
    __syncthreads();

    // ---- accumulators: C[mi][ni][4], 128 fp32 per thread
    float c[4][8][4];
    #pragma unroll
    for (int mi = 0; mi < 4; mi++)
        #pragma unroll
        for (int ni = 0; ni < 8; ni++)
            #pragma unroll
            for (int jj = 0; jj < 4; jj++) c[mi][ni][jj] = 0.f;

    // per-warp base offsets
    const uint32_t a_mbase = (uint32_t)(wm * 64 + lrow) * (APITCH * 2);
    const uint32_t w_nbase = (uint32_t)(wn * 64 + lrow) * 80;

    // ---- 16 chunks of K=32: layer = g>>3, kc = g&7; double-buffered cp.async
    #pragma unroll 1
    for (int g = 0; g < 16; g++) {
        const int kc = g & 7;
        const char* wbufH = smem + SM_W + (g & 1) * (2 * WBUF_BYTES);
        const char* wbufL = wbufH + WBUF_BYTES;

        // prefetch next chunk
        if (g + 1 < 16) {
            const __nv_bfloat16* Wh = g_wt + (size_t)((g + 1) >> 3) * 131072;
            const int nkc = (g + 1) & 7;
            const uint32_t dbase = sbase + SM_W + ((g + 1) & 1) * (2 * WBUF_BYTES);
            #pragma unroll
            for (int it = 0; it < 8; it++) {
                int u = tid + (it & 3) * 256;
                int n = u >> 2, j = u & 3;
                const __nv_bfloat16* src = Wh + (it < 4 ? 0 : 65536) + n * 256 + nkc * 32 + j * 8;
                cp16(dbase + (it < 4 ? 0 : WBUF_BYTES) + n * 80 + j * 16, src);
            }
            CP_COMMIT();
        }

        // compute on current chunk: 2 k16 steps
        #pragma unroll
        for (int ks = 0; ks < 2; ks++) {
            const uint32_t akoff = (uint32_t)(kc * 32 + ks * 16 + lc2) * 2;
            const uint32_t wkoff = (uint32_t)(ks * 16 + lc2) * 2;

            uint32_t af[4][4], bh[8][2], bl[8][2];
            #pragma unroll
            for (int mi = 0; mi < 4; mi++) {
                uint32_t base = a_mbase + (uint32_t)mi * 16 * (APITCH * 2) + akoff;
                af[mi][0] = *(const uint32_t*)(smem + SM_AH + base);
                af[mi][1] = *(const uint32_t*)(smem + SM_AH + base + 8 * APITCH * 2);
                af[mi][2] = *(const uint32_t*)(smem + SM_AH + base + 16);
                af[mi][3] = *(const uint32_t*)(smem + SM_AH + base + 8 * APITCH * 2 + 16);
            }
            #pragma unroll
            for (int ni = 0; ni < 8; ni++) {
                uint32_t bo = w_nbase + (uint32_t)ni * 8 * 80 + wkoff;
                bh[ni][0] = *(const uint32_t*)(wbufH + bo);
                bh[ni][1] = *(const uint32_t*)(wbufH + bo + 16);
                bl[ni][0] = *(const uint32_t*)(wbufL + bo);
                bl[ni][1] = *(const uint32_t*)(wbufL + bo + 16);
            }
            // Ah*Bh
            #pragma unroll
            for (int mi = 0; mi < 4; mi++)
                #pragma unroll
                for (int ni = 0; ni < 8; ni++)
                    mma_bf16(c[mi][ni], af[mi], bh[ni]);
            // Ah*Bl
            #pragma unroll
            for (int mi = 0; mi < 4; mi++)
                #pragma unroll
                for (int ni = 0; ni < 8; ni++)
                    mma_bf16(c[mi][ni], af[mi], bl[ni]);
            // Al*Bh (reload A from lo buffer)
            #pragma unroll
            for (int mi = 0; mi < 4; mi++) {
                uint32_t base = a_mbase + (uint32_t)mi * 16 * (APITCH * 2) + akoff;
                af[mi][0] = *(const uint32_t*)(smem + SM_AL + base);
                af[mi][1] = *(const uint32_t*)(smem + SM_AL + base + 8 * APITCH * 2);
                af[mi][2] = *(const uint32_t*)(smem + SM_AL + base + 16);
                af[mi][3] = *(const uint32_t*)(smem + SM_AL + base + 8 * APITCH * 2 + 16);
            }
            #pragma unroll
            for (int mi = 0; mi < 4; mi++)
                #pragma unroll
                for (int ni = 0; ni < 8; ni++)
                    mma_bf16(c[mi][ni], af[mi], bh[ni]);
        }

        CP_WAIT0();
        __syncthreads();

        // ---- between layers: h1 = relu(D + b1) -> split -> A SMEM; reset accum
        if (g == 7) {
            // (sync above already separates layer-1 A reads from these writes)
            #pragma unroll
            for (int ni = 0; ni < 8; ni++) {
                int n = wn * 64 + ni * 8 + lc2;
                float2 bb = *(const float2*)(b1 + n);
                #pragma unroll
                for (int mi = 0; mi < 4; mi++) {
                    int m1 = wm * 64 + mi * 16 + lrow;
                    float x0 = frelu(c[mi][ni][0] + bb.x);
                    float x1 = frelu(c[mi][ni][1] + bb.y);
                    float y0 = frelu(c[mi][ni][2] + bb.x);
                    float y1 = frelu(c[mi][ni][3] + bb.y);
                    uint32_t h, l;
                    uint32_t off1 = (uint32_t)m1 * (APITCH * 2) + n * 2;
                    split2(x0, x1, h, l);
                    *(uint32_t*)(smem + SM_AH + off1) = h;
                    *(uint32_t*)(smem + SM_AL + off1) = l;
                    uint32_t off2 = off1 + 8 * (APITCH * 2);
                    split2(y0, y1, h, l);
                    *(uint32_t*)(smem + SM_AH + off2) = h;
                    *(uint32_t*)(smem + SM_AL + off2) = l;
                    c[mi][ni][0] = 0.f; c[mi][ni][1] = 0.f;
                    c[mi][ni][2] = 0.f; c[mi][ni][3] = 0.f;
                }
            }
            __syncthreads();
        }
    }

    // ---- final epilogue: logit = relu(D + b2) . Wf + bf
    float* part = (float*)(smem + SM_PART);
    float ps1[4], ps2[4];
    #pragma unroll
    for (int mi = 0; mi < 4; mi++) { ps1[mi] = 0.f; ps2[mi] = 0.f; }
    #pragma unroll
    for (int ni = 0; ni < 8; ni++) {
        int n = wn * 64 + ni * 8 + lc2;
        float2 bb = *(const float2*)(b2 + n);
        float2 wf = *(const float2*)(Wf + n);
        #pragma unroll
        for (int mi = 0; mi < 4; mi++) {
            ps1[mi] = fmaf(frelu(c[mi][ni][0] + bb.x), wf.x, ps1[mi]);
            ps1[mi] = fmaf(frelu(c[mi][ni][1] + bb.y), wf.y, ps1[mi]);
            ps2[mi] = fmaf(frelu(c[mi][ni][2] + bb.x), wf.x, ps2[mi]);
            ps2[mi] = fmaf(frelu(c[mi][ni][3] + bb.y), wf.y, ps2[mi]);
        }
    }
    #pragma unroll
    for (int mi = 0; mi < 4; mi++) {
        ps1[mi] += __shfl_xor_sync(0xffffffffu, ps1[mi], 1);
        ps1[mi] += __shfl_xor_sync(0xffffffffu, ps1[mi], 2);
        ps2[mi] += __shfl_xor_sync(0xffffffffu, ps2[mi], 1);
        ps2[mi] += __shfl_xor_sync(0xffffffffu, ps2[mi], 2);
    }
    if ((lt & 3) == 0) {
        #pragma unroll
        for (int mi = 0; mi < 4; mi++) {
            int m1 = wm * 64 + mi * 16 + lrow;
            part[wn * 128 + m1]     = ps1[mi];
            part[wn * 128 + m1 + 8] = ps2[mi];
        }
    }
    __syncthreads();
    if (tid < 128) {
        float s = part[tid] + part[128 + tid] + part[256 + tid] + part[384 + tid]
                + __ldg(bf);
        out[(size_t)qrow * SKd + kb * 128 + tid] = s;
    }
}

// ---------------------------------------------------------------------------
// Launch
// ---------------------------------------------------------------------------
extern "C" void kernel_launch(void* const* d_in, const int* in_sizes, int n_in,
                              void* d_out, int out_size)
{
    (void)in_sizes; (void)n_in; (void)out_size;
    const float* query = (const float*)d_in[0];
    const float* key_  = (const float*)d_in[1];
    const float* Wqe   = (const float*)d_in[2];
    const float* bqe   = (const float*)d_in[3];
    const float* Wke   = (const float*)d_in[4];
    const float* bke   = (const float*)d_in[5];
    const float* W0    = (const float*)d_in[6];
    const float* b0    = (const float*)d_in[7];
    const float* W1    = (const float*)d_in[8];
    const float* b1    = (const float*)d_in[9];
    const float* W2    = (const float*)d_in[10];
    const float* b2    = (const float*)d_in[11];
    const float* Wf    = (const float*)d_in[12];
    const float* bf    = (const float*)d_in[13];
    const float* Wv1   = (const float*)d_in[14];
    const float* bv1   = (const float*)d_in[15];
    const float* Wv2   = (const float*)d_in[16];
    const float* bv2   = (const float*)d_in[17];
    float* out = (float*)d_out;

    void* sp = nullptr;
    cudaGetSymbolAddress(&sp, g_scratch);
    float* S = (float*)sp;

    cudaFuncSetAttribute(pair_mma_kernel,
                         cudaFuncAttributeMaxDynamicSharedMemorySize, SMEM_TOTAL);

    // Encoders
    gemm_bias_act_kernel<<<dim3(4, NQ / 32), 256>>>(query, Wqe, bqe, S + OFF_QF, NQ, Ed, 1);
    gemm_bias_act_kernel<<<dim3(4, NK / 32), 256>>>(key_,  Wke, bke, S + OFF_KF, NK, Ed, 1);
    // Weight transpose + hi/lo split
    transpose_split_kernel<<<dim3(2, 64), 256>>>(W1, W2);
    // Projections
    gemm_bias_act_kernel<<<dim3(4, NQ / 32), 256>>>(S + OFF_QF, W0,            nullptr, S + OFF_QP, NQ, Hd, 0);
    gemm_bias_act_kernel<<<dim3(4, NK / 32), 256>>>(S + OFF_KF, W0 + Hd * Hd,  nullptr, S + OFF_KP, NK, Hd, 0);
    gemm_bias_act_kernel<<<dim3(4, NQ / 32), 256>>>(S + OFF_QF, Wv1,           nullptr, S + OFF_QV, NQ, Hd, 0);
    gemm_bias_act_kernel<<<dim3(4, NK / 32), 256>>>(S + OFF_KF, Wv1 + Hd * Hd, nullptr, S + OFF_KV, NK, Hd, 0);

    // Fused HMMA pair MLP
    pair_mma_kernel<<<dim3(SKd / 128, SQd, Bsz), 256, SMEM_TOTAL>>>(
        b0, b1, b2, Wf, bf, bv1, Wv2, bv2, out);
}

// round 5
// speedup vs baseline: 2.5366x; 1.0336x over previous
#include <cuda_runtime.h>
#include <cuda_bf16.h>
#include <math.h>
#include <cstdint>

// Problem constants
#define Bsz 2
#define SQd 256
#define SKd 512
#define Ed  512
#define Hd  256

#define NQ (Bsz*SQd)   // 512
#define NK (Bsz*SKd)   // 1024
#define OFF_QF 0
#define OFF_KF (OFF_QF + NQ*Hd)
#define OFF_QP (OFF_KF + NK*Hd)
#define OFF_KP (OFF_QP + NQ*Hd)
#define OFF_QV (OFF_KP + NK*Hd)
#define OFF_KV (OFF_QV + NQ*Hd)
#define SCRATCH_FLOATS (OFF_KV + NK*Hd)

__device__ float g_scratch[SCRATCH_FLOATS];
// Transposed + hi/lo split weights: [W1h][W1l][W2h][W2l], each [256 n][256 k] bf16
__device__ __align__(16) __nv_bfloat16 g_wt[4 * 256 * 256];

__device__ __forceinline__ float frelu(float x) { return x > 0.f ? x : 0.f; }
__device__ __forceinline__ float4 ldg4(const float* p) { return __ldg((const float4*)p); }

__device__ __forceinline__ uint32_t smem_to_u32(const void* p) {
    uint32_t a;
    asm("{ .reg .u64 t; cvta.to.shared.u64 t, %1; cvt.u32.u64 %0, t; }" : "=r"(a) : "l"(p));
    return a;
}
__device__ __forceinline__ void cp16(uint32_t dst, const void* src) {
    asm volatile("cp.async.cg.shared.global [%0], [%1], 16;" :: "r"(dst), "l"(src));
}
#define CP_COMMIT() asm volatile("cp.async.commit_group;" ::: "memory")
#define CP_WAIT0()  asm volatile("cp.async.wait_group 0;" ::: "memory")

// mma.sync m16n8k16 bf16 -> f32, accumulate in place
__device__ __forceinline__ void mma_bf16(float* c, const uint32_t* a, const uint32_t* b) {
    asm volatile(
        "mma.sync.aligned.m16n8k16.row.col.f32.bf16.bf16.f32 "
        "{%0,%1,%2,%3}, {%4,%5,%6,%7}, {%8,%9}, {%0,%1,%2,%3};"
        : "+f"(c[0]), "+f"(c[1]), "+f"(c[2]), "+f"(c[3])
        : "r"(a[0]), "r"(a[1]), "r"(a[2]), "r"(a[3]), "r"(b[0]), "r"(b[1]));
}
__device__ __forceinline__ void ldsm4(uint32_t* r, uint32_t addr) {
    asm volatile("ldmatrix.sync.aligned.m8n8.x4.shared.b16 {%0,%1,%2,%3}, [%4];"
                 : "=r"(r[0]), "=r"(r[1]), "=r"(r[2]), "=r"(r[3]) : "r"(addr));
}

__device__ __forceinline__ void split2(float x0, float x1, uint32_t& h, uint32_t& l) {
    __nv_bfloat16 h0 = __float2bfloat16(x0), h1 = __float2bfloat16(x1);
    float r0 = x0 - __bfloat162float(h0), r1 = x1 - __bfloat162float(h1);
    __nv_bfloat16 l0 = __float2bfloat16(r0), l1 = __float2bfloat16(r1);
    h = (uint32_t)__bfloat16_as_ushort(h0) | ((uint32_t)__bfloat16_as_ushort(h1) << 16);
    l = (uint32_t)__bfloat16_as_ushort(l0) | ((uint32_t)__bfloat16_as_ushort(l1) << 16);
}

// ---------------------------------------------------------------------------
// Prep GEMM tile (device function; verified logic from R2)
// C[row0..row0+32, col0..col0+64] = act(A[row0.., :K] @ W[:, col0..] (+bias))
// ---------------------------------------------------------------------------
__device__ void gemm_tile(const float* __restrict__ A,
                          const float* __restrict__ W,
                          const float* __restrict__ bias,
                          float* __restrict__ C,
                          int K, int act, int row0, int col0)
{
    __shared__ float As[32 * 32];
    __shared__ float Ws[32 * 64];
    const int tid = threadIdx.x;
    const int tr  = tid >> 4;
    const int tc  = tid & 15;

    float acc0x=0.f,acc0y=0.f,acc0z=0.f,acc0w=0.f,acc1x=0.f,acc1y=0.f,acc1z=0.f,acc1w=0.f;
    if (bias) {
        float4 bb = ldg4(bias + col0 + tc * 4);
        acc0x=bb.x;acc0y=bb.y;acc0z=bb.z;acc0w=bb.w;
        acc1x=bb.x;acc1y=bb.y;acc1z=bb.z;acc1w=bb.w;
    }
    for (int kc = 0; kc < K; kc += 32) {
        __syncthreads();
        {   int r = tid >> 3; int ck = (tid & 7) * 4;
            *(float4*)(As + r * 32 + ck) = ldg4(A + (size_t)(row0 + r) * K + kc + ck); }
        {
            #pragma unroll
            for (int i = 0; i < 2; i++) {
                int f = tid + 256 * i; int k = f >> 4; int c = (f & 15) * 4;
                *(float4*)(Ws + k * 64 + c) = ldg4(W + (size_t)(kc + k) * 256 + col0 + c);
            } }
        __syncthreads();
        #pragma unroll 8
        for (int k = 0; k < 32; k++) {
            float a0 = As[(tr * 2) * 32 + k];
            float a1 = As[(tr * 2 + 1) * 32 + k];
            float4 w = *(float4*)(Ws + k * 64 + tc * 4);
            acc0x = fmaf(a0, w.x, acc0x); acc0y = fmaf(a0, w.y, acc0y);
            acc0z = fmaf(a0, w.z, acc0z); acc0w = fmaf(a0, w.w, acc0w);
            acc1x = fmaf(a1, w.x, acc1x); acc1y = fmaf(a1, w.y, acc1y);
            acc1z = fmaf(a1, w.z, acc1z); acc1w = fmaf(a1, w.w, acc1w);
        }
    }
    if (act) {
        acc0x=frelu(acc0x);acc0y=frelu(acc0y);acc0z=frelu(acc0z);acc0w=frelu(acc0w);
        acc1x=frelu(acc1x);acc1y=frelu(acc1y);acc1z=frelu(acc1z);acc1w=frelu(acc1w);
    }
    *(float4*)(C + (size_t)(row0+tr*2)  *256 + col0 + tc*4) = make_float4(acc0x,acc0y,acc0z,acc0w);
    *(float4*)(C + (size_t)(row0+tr*2+1)*256 + col0 + tc*4) = make_float4(acc1x,acc1y,acc1z,acc1w);
}

// Launch 1: both encoders in one kernel. grid (4, 48)
__global__ void encoder_kernel(const float* __restrict__ query,
                               const float* __restrict__ key_,
                               const float* __restrict__ Wqe, const float* __restrict__ bqe,
                               const float* __restrict__ Wke, const float* __restrict__ bke)
{
    float* S = g_scratch;
    int y = blockIdx.y;
    if (y < 16)
        gemm_tile(query, Wqe, bqe, S + OFF_QF, Ed, 1, y * 32, blockIdx.x * 64);
    else
        gemm_tile(key_,  Wke, bke, S + OFF_KF, Ed, 1, (y - 16) * 32, blockIdx.x * 64);
}

// Launch 2: 4 projections + weight transpose/split. grid (4, 32, 5)
__global__ void proj_trans_kernel(const float* __restrict__ W0,
                                  const float* __restrict__ Wv1,
                                  const float* __restrict__ W1,
                                  const float* __restrict__ W2)
{
    float* S = g_scratch;
    const int z = blockIdx.z;
    if (z < 4) {
        const float* A; const float* W; float* C;
        switch (z) {
            case 0: A = S + OFF_QF; W = W0;            C = S + OFF_QP; break;
            case 1: A = S + OFF_KF; W = W0 + Hd * Hd;  C = S + OFF_KP; break;
            case 2: A = S + OFF_QF; W = Wv1;           C = S + OFF_QV; break;
            default:A = S + OFF_KF; W = Wv1 + Hd * Hd; C = S + OFF_KV; break;
        }
        int M = (z == 1 || z == 3) ? 1024 : 512;
        if (blockIdx.y * 32 >= M) return;
        gemm_tile(A, W, nullptr, C, Hd, 0, blockIdx.y * 32, blockIdx.x * 64);
    } else {
        // transpose + hi/lo split of W1, W2 into g_wt (Wt[n][k] row-major)
        int lin = blockIdx.y * 4 + blockIdx.x;      // 0..127
        const float* W = (lin >= 64) ? W2 : W1;
        __nv_bfloat16* oh = g_wt + (size_t)(lin >= 64 ? 2 : 0) * 65536;
        __nv_bfloat16* ol = oh + 65536;
        int base = (lin & 63) * 1024;
        #pragma unroll
        for (int t = 0; t < 4; t++) {
            int e = base + t * 256 + threadIdx.x;
            int n = e >> 8, k = e & 255;
            float w = __ldg(W + (size_t)k * 256 + n);
            __nv_bfloat16 h = __float2bfloat16(w);
            __nv_bfloat16 l = __float2bfloat16(w - __bfloat162float(h));
            oh[e] = h; ol[e] = l;
        }
    }
}

// ---------------------------------------------------------------------------
// HMMA fused pair kernel. CTA = (b, q, 128 k-pairs). M=128, N=256, K=256.
// 8 warps: 2 (M, 64 each) x 4 (N, 64 each). 3-term bf16 split, ldmatrix loads.
// ---------------------------------------------------------------------------
#define APITCH 264                       // bf16 elems per A row (528 B)
#define SM_AH 0
#define SM_AL (128 * APITCH * 2)         // 67584
#define SM_W  (2 * 128 * APITCH * 2)     // 135168
#define WBUF_BYTES (256 * 40 * 2)        // 20480 (one of H/L), pitch 80 B
#define SM_PART (SM_W + 4 * WBUF_BYTES)  // 217088
#define SMEM_TOTAL (SM_PART + 512 * 4)   // 219136

__global__ void __launch_bounds__(256, 1)
pair_mma_kernel(const float* __restrict__ b0, const float* __restrict__ b1,
                const float* __restrict__ b2,
                const float* __restrict__ Wf, const float* __restrict__ bf,
                const float* __restrict__ bv1, const float* __restrict__ Wv2,
                const float* __restrict__ bv2,
                float* __restrict__ out)
{
    extern __shared__ char smem[];
    const uint32_t sbase = smem_to_u32(smem);

    const int tid = threadIdx.x;
    const int w   = tid >> 5;
    const int wm  = w >> 2;            // 0..1 : M group (64 rows)
    const int wn  = w & 3;             // 0..3 : N group (64 cols)
    const int lt  = tid & 31;
    const int lrow = lt >> 2;          // 0..7
    const int lc2  = (lt & 3) * 2;     // 0,2,4,6

    // ldmatrix per-lane row offsets (constant across the k loop)
    const uint32_t a_rowoff = (uint32_t)(wm * 64 + (lt & 15)) * (APITCH * 2)
                            + (uint32_t)((lt >> 4) * 8) * 2;
    const uint32_t b_rowoff = (uint32_t)(wn * 64 + (lt & 7) + ((lt >> 4) & 1) * 8) * 80
                            + (uint32_t)((lt >> 3) & 1) * 16;

    const int kb = blockIdx.x, q = blockIdx.y, b = blockIdx.z;
    const int qrow  = b * SQd + q;
    const int krow0 = b * SKd + kb * 128;

    const float* qp = g_scratch + OFF_QP + (size_t)qrow  * Hd;
    const float* kp = g_scratch + OFF_KP + (size_t)krow0 * Hd;
    const float* qv = g_scratch + OFF_QV + (size_t)qrow  * Hd;
    const float* kv = g_scratch + OFF_KV + (size_t)krow0 * Hd;

    // ---- prefetch W chunk 0 (layer 0) via cp.async while we do fp32 work
    {
        #pragma unroll
        for (int it = 0; it < 8; it++) {
            int u = tid + (it & 3) * 256;       // 0..1023
            int n = u >> 2, j = u & 3;
            const __nv_bfloat16* src = g_wt + (it < 4 ? 0 : 65536) + n * 256 + j * 8;
            uint32_t dst = sbase + SM_W + (it < 4 ? 0 : WBUF_BYTES) + n * 80 + j * 16;
            cp16(dst, src);
        }
        CP_COMMIT();
    }

    // ---- variance branch: v = relu(qv+kv+bv1); softplus(v.Wv2 + bv2)
    {
        const int r = tid >> 1, part = tid & 1;
        const float* qvr = qv + part * 128;
        const float* kvr = kv + (size_t)r * Hd + part * 128;
        const float* bvr = bv1 + part * 128;
        const float* wvr = Wv2 + part * 128;
        float s = 0.f;
        #pragma unroll
        for (int i = 0; i < 32; i++) {
            float4 a = ldg4(qvr + i * 4);
            float4 c = ldg4(kvr + i * 4);
            float4 bb = ldg4(bvr + i * 4);
            float4 ww = ldg4(wvr + i * 4);
            s = fmaf(frelu(a.x + c.x + bb.x), ww.x, s);
            s = fmaf(frelu(a.y + c.y + bb.y), ww.y, s);
            s = fmaf(frelu(a.z + c.z + bb.z), ww.z, s);
            s = fmaf(frelu(a.w + c.w + bb.w), ww.w, s);
        }
        s += __shfl_down_sync(0xffffffffu, s, 1);
        if (part == 0) {
            float x = s + __ldg(bv2);
            out[(size_t)Bsz * SQd * SKd + (size_t)qrow * SKd + kb * 128 + r] =
                fmaxf(x, 0.f) + log1pf(expf(-fabsf(x)));
        }
    }

    // ---- build A = relu(qp + kp + b0), hi/lo split -> SMEM
    {
        const int row = tid >> 1, half = (tid & 1) * 128;
        const float* qpr = qp + half;
        const float* kpr = kp + (size_t)row * Hd + half;
        const float* b0r = b0 + half;
        #pragma unroll
        for (int j4 = 0; j4 < 32; j4++) {
            float4 a  = ldg4(qpr + j4 * 4);
            float4 c  = ldg4(kpr + j4 * 4);
            float4 bb = ldg4(b0r + j4 * 4);
            float x0 = frelu(a.x + c.x + bb.x);
            float x1 = frelu(a.y + c.y + bb.y);
            float x2 = frelu(a.z + c.z + bb.z);
            float x3 = frelu(a.w + c.w + bb.w);
            uint32_t h0, l0, h1, l1;
            split2(x0, x1, h0, l0);
            split2(x2, x3, h1, l1);
            uint32_t off = (uint32_t)row * (APITCH * 2) + (half + j4 * 4) * 2;
            *(uint2*)(smem + SM_AH + off) = make_uint2(h0, h1);
            *(uint2*)(smem + SM_AL + off) = make_uint2(l0, l1);
        }
    }
    CP_WAIT0();
    __syncthreads();

    // ---- accumulators: C[mi][ni][4], 128 fp32 per thread
    float c[4][8][4];
    #pragma unroll
    for (int mi = 0; mi < 4; mi++)
        #pragma unroll
        for (int ni = 0; ni < 8; ni++)
            #pragma unroll
            for (int jj = 0; jj < 4; jj++) c[mi][ni][jj] = 0.f;

    // ---- 16 chunks of K=32: layer = g>>3, kc = g&7; double-buffered cp.async
    #pragma unroll 1
    for (int g = 0; g < 16; g++) {
        const int kc = g & 7;
        const uint32_t wbufH = sbase + SM_W + (uint32_t)(g & 1) * (2 * WBUF_BYTES);
        const uint32_t wbufL = wbufH + WBUF_BYTES;

        // prefetch next chunk
        if (g + 1 < 16) {
            const __nv_bfloat16* Wh = g_wt + (size_t)((g + 1) >> 3) * 131072;
            const int nkc = (g + 1) & 7;
            const uint32_t dbase = sbase + SM_W + ((g + 1) & 1) * (2 * WBUF_BYTES);
            #pragma unroll
            for (int it = 0; it < 8; it++) {
                int u = tid + (it & 3) * 256;
                int n = u >> 2, j = u & 3;
                const __nv_bfloat16* src = Wh + (it < 4 ? 0 : 65536) + n * 256 + nkc * 32 + j * 8;
                cp16(dbase + (it < 4 ? 0 : WBUF_BYTES) + n * 80 + j * 16, src);
            }
            CP_COMMIT();
        }

        // compute on current chunk: 2 k16 steps, ldmatrix fragment loads
        #pragma unroll
        for (int ks = 0; ks < 2; ks++) {
            const uint32_t a_k = (uint32_t)(kc * 32 + ks * 16) * 2;
            const uint32_t b_k = (uint32_t)ks * 32;

            uint32_t afh[4][4], afl[4][4], bh[8][2], bl[8][2];
            #pragma unroll
            for (int mi = 0; mi < 4; mi++)
                ldsm4(afh[mi], sbase + SM_AH + a_rowoff + (uint32_t)mi * 16 * (APITCH * 2) + a_k);
            #pragma unroll
            for (int np = 0; np < 4; np++) {
                uint32_t r[4];
                ldsm4(r, wbufH + b_rowoff + (uint32_t)np * 16 * 80 + b_k);
                bh[2*np][0] = r[0]; bh[2*np][1] = r[1];
                bh[2*np+1][0] = r[2]; bh[2*np+1][1] = r[3];
            }
            // Ah*Bh
            #pragma unroll
            for (int mi = 0; mi < 4; mi++)
                #pragma unroll
                for (int ni = 0; ni < 8; ni++)
                    mma_bf16(c[mi][ni], afh[mi], bh[ni]);
            #pragma unroll
            for (int np = 0; np < 4; np++) {
                uint32_t r[4];
                ldsm4(r, wbufL + b_rowoff + (uint32_t)np * 16 * 80 + b_k);
                bl[2*np][0] = r[0]; bl[2*np][1] = r[1];
                bl[2*np+1][0] = r[2]; bl[2*np+1][1] = r[3];
            }
            // Ah*Bl
            #pragma unroll
            for (int mi = 0; mi < 4; mi++)
                #pragma unroll
                for (int ni = 0; ni < 8; ni++)
                    mma_bf16(c[mi][ni], afh[mi], bl[ni]);
            #pragma unroll
            for (int mi = 0; mi < 4; mi++)
                ldsm4(afl[mi], sbase + SM_AL + a_rowoff + (uint32_t)mi * 16 * (APITCH * 2) + a_k);
            // Al*Bh
            #pragma unroll
            for (int mi = 0; mi < 4; mi++)
                #pragma unroll
                for (int ni = 0; ni < 8; ni++)
                    mma_bf16(c[mi][ni], afl[mi], bh[ni]);
        }

        CP_WAIT0();
        __syncthreads();

        // ---- between layers: h1 = relu(D + b1) -> split -> A SMEM; reset accum
        if (g == 7) {
            #pragma unroll
            for (int ni = 0; ni < 8; ni++) {
                int n = wn * 64 + ni * 8 + lc2;
                float2 bb = *(const float2*)(b1 + n);
                #pragma unroll
                for (int mi = 0; mi < 4; mi++) {
                    int m1 = wm * 64 + mi * 16 + lrow;
                    float x0 = frelu(c[mi][ni][0] + bb.x);
                    float x1 = frelu(c[mi][ni][1] + bb.y);
                    float y0 = frelu(c[mi][ni][2] + bb.x);
                    float y1 = frelu(c[mi][ni][3] + bb.y);
                    uint32_t h, l;
                    uint32_t off1 = (uint32_t)m1 * (APITCH * 2) + n * 2;
                    split2(x0, x1, h, l);
                    *(uint32_t*)(smem + SM_AH + off1) = h;
                    *(uint32_t*)(smem + SM_AL + off1) = l;
                    uint32_t off2 = off1 + 8 * (APITCH * 2);
                    split2(y0, y1, h, l);
                    *(uint32_t*)(smem + SM_AH + off2) = h;
                    *(uint32_t*)(smem + SM_AL + off2) = l;
                    c[mi][ni][0] = 0.f; c[mi][ni][1] = 0.f;
                    c[mi][ni][2] = 0.f; c[mi][ni][3] = 0.f;
                }
            }
            __syncthreads();
        }
    }

    // ---- final epilogue: logit = relu(D + b2) . Wf + bf
    float* part = (float*)(smem + SM_PART);
    float ps1[4], ps2[4];
    #pragma unroll
    for (int mi = 0; mi < 4; mi++) { ps1[mi] = 0.f; ps2[mi] = 0.f; }
    #pragma unroll
    for (int ni = 0; ni < 8; ni++) {
        int n = wn * 64 + ni * 8 + lc2;
        float2 bb = *(const float2*)(b2 + n);
        float2 wf = *(const float2*)(Wf + n);
        #pragma unroll
        for (int mi = 0; mi < 4; mi++) {
            ps1[mi] = fmaf(frelu(c[mi][ni][0] + bb.x), wf.x, ps1[mi]);
            ps1[mi] = fmaf(frelu(c[mi][ni][1] + bb.y), wf.y, ps1[mi]);
            ps2[mi] = fmaf(frelu(c[mi][ni][2] + bb.x), wf.x, ps2[mi]);
            ps2[mi] = fmaf(frelu(c[mi][ni][3] + bb.y), wf.y, ps2[mi]);
        }
    }
    #pragma unroll
    for (int mi = 0; mi < 4; mi++) {
        ps1[mi] += __shfl_xor_sync(0xffffffffu, ps1[mi], 1);
        ps1[mi] += __shfl_xor_sync(0xffffffffu, ps1[mi], 2);
        ps2[mi] += __shfl_xor_sync(0xffffffffu, ps2[mi], 1);
        ps2[mi] += __shfl_xor_sync(0xffffffffu, ps2[mi], 2);
    }
    if ((lt & 3) == 0) {
        #pragma unroll
        for (int mi = 0; mi < 4; mi++) {
            int m1 = wm * 64 + mi * 16 + lrow;
            part[wn * 128 + m1]     = ps1[mi];
            part[wn * 128 + m1 + 8] = ps2[mi];
        }
    }
    __syncthreads();
    if (tid < 128) {
        float s = part[tid] + part[128 + tid] + part[256 + tid] + part[384 + tid]
                + __ldg(bf);
        out[(size_t)qrow * SKd + kb * 128 + tid] = s;
    }
}

// ---------------------------------------------------------------------------
// Launch (exactly 3 launches per call)
// ---------------------------------------------------------------------------
extern "C" void kernel_launch(void* const* d_in, const int* in_sizes, int n_in,
                              void* d_out, int out_size)
{
    (void)in_sizes; (void)n_in; (void)out_size;
    const float* query = (const float*)d_in[0];
    const float* key_  = (const float*)d_in[1];
    const float* Wqe   = (const float*)d_in[2];
    const float* bqe   = (const float*)d_in[3];
    const float* Wke   = (const float*)d_in[4];
    const float* bke   = (const float*)d_in[5];
    const float* W0    = (const float*)d_in[6];
    const float* b0    = (const float*)d_in[7];
    const float* W1    = (const float*)d_in[8];
    const float* b1    = (const float*)d_in[9];
    const float* W2    = (const float*)d_in[10];
    const float* b2    = (const float*)d_in[11];
    const float* Wf    = (const float*)d_in[12];
    const float* bf    = (const float*)d_in[13];
    const float* Wv1   = (const float*)d_in[14];
    const float* bv1   = (const float*)d_in[15];
    const float* Wv2   = (const float*)d_in[16];
    const float* bv2   = (const float*)d_in[17];
    float* out = (float*)d_out;

    cudaFuncSetAttribute(pair_mma_kernel,
                         cudaFuncAttributeMaxDynamicSharedMemorySize, SMEM_TOTAL);

    // 1: encoders (qf, kf)
    encoder_kernel<<<dim3(4, 48), 256>>>(query, key_, Wqe, bqe, Wke, bke);
    // 2: projections (qp,kp,qv,kv) + W1/W2 transpose-split
    proj_trans_kernel<<<dim3(4, 32, 5), 256>>>(W0, Wv1, W1, W2);
    // 3: fused HMMA pair MLP
    pair_mma_kernel<<<dim3(SKd / 128, SQd, Bsz), 256, SMEM_TOTAL>>>(
        b0, b1, b2, Wf, bf, bv1, Wv2, bv2, out);
}